// round 3
// baseline (speedup 1.0000x reference)
#include <cuda_runtime.h>
#include <cstdint>

// Problem constants (fixed by setup_inputs): x is [8, 512, 16384] fp32.
#define BATCH   8
#define NBANDS  8
#define FBAND   64          // 512 / 8
#define TLEN    16384
#define NDIFF   5
#define NAVG    11
#define NGAUSS  15
#define STRIP   2048        // time-strip per k_pool block (256 thr * 8 t)

// Scratch (allocation-free rule: __device__ globals)
__device__ float    g_pool[BATCH * NBANDS * TLEN];   // 4 MB
__device__ float    g_act [BATCH * TLEN];            // 512 KB
__device__ unsigned g_bmax[BATCH];

__device__ __forceinline__ float lg1p(float gam, float v) {
    // log1p(gam*v), arg of log in [1, ~11]: MUFU.LG2 path is plenty accurate here
    return __logf(fmaf(gam, v, 1.0f));
}

// ---------------------------------------------------------------------------
// Kernel 1: the 256 MB streamer.
// pool[b,c,t] = sum_f relu( sum_k diff_w[c,k]*log1p(gamma_c*x[b,c*64+f,t+k-2]) + diff_b[c] )
// Aligned LDG.128 only; logs computed ONCE per element and staged through smem
// (double-buffered, 1 barrier/row); 5-tap windows read back as 4x LDS.128.
// ---------------------------------------------------------------------------
__global__ void __launch_bounds__(256, 4) k_pool(
    const float* __restrict__ x,
    const float* __restrict__ log_gamma,
    const float* __restrict__ diff_w,      // [NBANDS,1,1,5] flat
    const float* __restrict__ diff_b)
{
    // smem row layout: index 4+i holds log of strip element i (i in [0,2048));
    // [2,3] = left halo (t=-2,-1), [2052,2053] = right halo (t=2048,2049).
    // [0,1] and [2054,2055] are alignment slack (read but never used).
    __shared__ float sbuf[2][2056];

    const int slab  = blockIdx.y;            // b*NBANDS + c
    const int c     = slab & (NBANDS - 1);
    const int tid   = threadIdx.x;
    const int strip = blockIdx.x * STRIP;

    // fold the per-batch max reset into this kernel (runs before k_act in stream order)
    if (blockIdx.x == 0 && (slab & 7) == 0 && tid == 0) g_bmax[slab >> 3] = 0u;

    const float gam = __expf(log_gamma[c]);
    const float w0 = diff_w[c * NDIFF + 0];
    const float w1 = diff_w[c * NDIFF + 1];
    const float w2 = diff_w[c * NDIFF + 2];
    const float w3 = diff_w[c * NDIFF + 3];
    const float w4 = diff_w[c * NDIFF + 4];
    const float db = diff_b[c];

    const bool hasL = (strip > 0);
    const bool hasR = (strip + STRIP < TLEN);

    // this thread's stream pointer within the slab/strip
    const float* base = x + (size_t)slab * FBAND * TLEN + strip + tid * 8;

    float acc[8];
    #pragma unroll
    for (int i = 0; i < 8; ++i) acc[i] = 0.f;

    float4 a0 = *reinterpret_cast<const float4*>(base);
    float4 b0 = *reinterpret_cast<const float4*>(base + 4);

    #pragma unroll 2
    for (int f = 0; f < FBAND; ++f) {
        // software-pipeline next row's loads (wrap-clamped; last prefetch is a hot re-read)
        const float* pn = base + (size_t)((f + 1) & (FBAND - 1)) * TLEN;
        const float4 a1 = *reinterpret_cast<const float4*>(pn);
        const float4 b1 = *reinterpret_cast<const float4*>(pn + 4);

        float* sb = sbuf[f & 1];

        // 8 logs for my 8 elements -> staged to smem (2x STS.128, conflict-free)
        const float4 r0 = make_float4(lg1p(gam, a0.x), lg1p(gam, a0.y),
                                      lg1p(gam, a0.z), lg1p(gam, a0.w));
        const float4 r1 = make_float4(lg1p(gam, b0.x), lg1p(gam, b0.y),
                                      lg1p(gam, b0.z), lg1p(gam, b0.w));
        *reinterpret_cast<float4*>(sb + 4 + tid * 8)     = r0;
        *reinterpret_cast<float4*>(sb + 4 + tid * 8 + 4) = r1;

        // block-edge halos (2 threads per block only)
        const float* p = base + (size_t)f * TLEN;
        if (tid == 0) {
            float h0 = 0.f, h1 = 0.f;
            if (hasL) { h0 = lg1p(gam, p[-2]); h1 = lg1p(gam, p[-1]); }
            sb[2] = h0; sb[3] = h1;
        }
        if (tid == 255) {
            float h0 = 0.f, h1 = 0.f;
            if (hasR) { h0 = lg1p(gam, p[8]); h1 = lg1p(gam, p[9]); }
            sb[2052] = h0; sb[2053] = h1;
        }
        __syncthreads();

        // read back 16-float window [t0-4, t0+12) as 4 aligned LDS.128
        const float4 q0 = *reinterpret_cast<const float4*>(sb + tid * 8);
        const float4 q1 = *reinterpret_cast<const float4*>(sb + tid * 8 + 4);
        const float4 q2 = *reinterpret_cast<const float4*>(sb + tid * 8 + 8);
        const float4 q3 = *reinterpret_cast<const float4*>(sb + tid * 8 + 12);
        const float L[16] = { q0.x, q0.y, q0.z, q0.w,  q1.x, q1.y, q1.z, q1.w,
                              q2.x, q2.y, q2.z, q2.w,  q3.x, q3.y, q3.z, q3.w };

        #pragma unroll
        for (int i = 0; i < 8; ++i) {
            // output t0+i uses logs of t0+i-2 .. t0+i+2 == L[i+2 .. i+6]
            float d = fmaf(w0, L[i + 2],
                      fmaf(w1, L[i + 3],
                      fmaf(w2, L[i + 4],
                      fmaf(w3, L[i + 5], w4 * L[i + 6])))) + db;
            acc[i] += fmaxf(d, 0.f);   // A_LRELU = 0 -> relu
        }

        a0 = a1; b0 = b1;
    }

    float* o = g_pool + (size_t)slab * TLEN + strip + tid * 8;
    *reinterpret_cast<float4*>(o)     = make_float4(acc[0], acc[1], acc[2], acc[3]);
    *reinterpret_cast<float4*>(o + 4) = make_float4(acc[4], acc[5], acc[6], acc[7]);
}

// ---------------------------------------------------------------------------
// Kernel 2: mix + avg + gauss + relu + per-batch max. Wide grid (16 x 8 blocks).
//   u[t] = sum_c mix_w[c] * pool[b,c,t]
//   m[t] = u[t] - (avg_w (x) u)[t] - sum_c mix_w[c]*avg_b[c]   (band-uniform avg_w)
//   act  = relu((gauss_w (x) m)[t] + gauss_b)
// ---------------------------------------------------------------------------
#define ACHUNK 1024
#define UH 12      // 5 (avg) + 7 (gauss)
#define MH 7

__global__ void __launch_bounds__(256) k_act(
    const float* __restrict__ avg_w,    // [8,1,11] flat; band-0 taps (uniform)
    const float* __restrict__ avg_b,
    const float* __restrict__ mix_w,
    const float* __restrict__ gauss_w,  // [1,1,15] flat
    const float* __restrict__ gauss_b)
{
    __shared__ float su[ACHUNK + 2 * UH];
    __shared__ float sm[ACHUNK + 2 * MH];
    __shared__ float sred[8];

    const int b   = blockIdx.y;
    const int t0  = blockIdx.x * ACHUNK;
    const int tid = threadIdx.x;

    float mw[NBANDS];
    #pragma unroll
    for (int c = 0; c < NBANDS; ++c) mw[c] = mix_w[c];
    float aw[NAVG];
    #pragma unroll
    for (int k = 0; k < NAVG; ++k) aw[k] = avg_w[k];
    float CB = 0.f;
    #pragma unroll
    for (int c = 0; c < NBANDS; ++c) CB = fmaf(mw[c], avg_b[c], CB);
    float gw[NGAUSS];
    #pragma unroll
    for (int k = 0; k < NGAUSS; ++k) gw[k] = gauss_w[k];
    const float gb = gauss_b[0];

    const float* pb = g_pool + (size_t)b * NBANDS * TLEN;

    // stage u chunk + halo (zero-padded outside [0, TLEN)); u computed on the fly
    for (int i = tid; i < ACHUNK + 2 * UH; i += 256) {
        const int gt = t0 - UH + i;
        float v = 0.f;
        if (gt >= 0 && gt < TLEN) {
            #pragma unroll
            for (int c = 0; c < NBANDS; ++c)
                v = fmaf(mw[c], pb[c * TLEN + gt], v);
        }
        su[i] = v;
    }
    __syncthreads();

    // m chunk + halo (m zero-padded outside [0, TLEN) for the gauss conv)
    for (int i = tid; i < ACHUNK + 2 * MH; i += 256) {
        const int gt = t0 - MH + i;
        float mval = 0.f;
        if (gt >= 0 && gt < TLEN) {
            const int bidx = i + (UH - MH);   // su index of global gt
            float a = 0.f;
            #pragma unroll
            for (int k = 0; k < NAVG; ++k)
                a = fmaf(aw[k], su[bidx + k - 5], a);
            mval = su[bidx] - a - CB;
        }
        sm[i] = mval;
    }
    __syncthreads();

    float mx = 0.f;
    float* ao = g_act + (size_t)b * TLEN + t0;
    #pragma unroll
    for (int j = 0; j < ACHUNK / 256; ++j) {
        const int tl = tid + j * 256;
        float g = gb;
        #pragma unroll
        for (int k = 0; k < NGAUSS; ++k)
            g = fmaf(gw[k], sm[tl + k], g);
        const float a = fmaxf(g, 0.f);
        ao[tl] = a;
        mx = fmaxf(mx, a);
    }

    // block max reduce -> atomicMax (values >= 0, so uint order == float order)
    #pragma unroll
    for (int o = 16; o > 0; o >>= 1)
        mx = fmaxf(mx, __shfl_xor_sync(0xffffffffu, mx, o));
    if ((tid & 31) == 0) sred[tid >> 5] = mx;
    __syncthreads();
    if (tid < 8) {
        mx = sred[tid];
        #pragma unroll
        for (int o = 4; o > 0; o >>= 1)
            mx = fmaxf(mx, __shfl_xor_sync(0xffu, mx, o));
        if (tid == 0) atomicMax(&g_bmax[b], __float_as_uint(mx));
    }
}

// ---------------------------------------------------------------------------
// Kernel 3: out = act / (max_b + 1e-8)
// ---------------------------------------------------------------------------
__global__ void __launch_bounds__(256) k_norm(float* __restrict__ out)
{
    const int v = blockIdx.x * 256 + threadIdx.x;   // float4 index over BATCH*TLEN/4
    const int b = v / (TLEN / 4);
    const float mxv = __uint_as_float(g_bmax[b]);
    const float inv = 1.0f / (mxv + 1e-8f);
    float4 q = reinterpret_cast<const float4*>(g_act)[v];
    q.x *= inv; q.y *= inv; q.z *= inv; q.w *= inv;
    reinterpret_cast<float4*>(out)[v] = q;
}

// ---------------------------------------------------------------------------
// Inputs (metadata order): x, log_gamma, diff_w, diff_b, avg_w, avg_b,
//                          mix_w, gauss_w, gauss_b. Output: [8, 16384] fp32.
// ---------------------------------------------------------------------------
extern "C" void kernel_launch(void* const* d_in, const int* in_sizes, int n_in,
                              void* d_out, int out_size)
{
    const float* x         = (const float*)d_in[0];
    const float* log_gamma = (const float*)d_in[1];
    const float* diff_w    = (const float*)d_in[2];
    const float* diff_b    = (const float*)d_in[3];
    const float* avg_w     = (const float*)d_in[4];
    const float* avg_b     = (const float*)d_in[5];
    const float* mix_w     = (const float*)d_in[6];
    const float* gauss_w   = (const float*)d_in[7];
    const float* gauss_b   = (const float*)d_in[8];
    float* out = (float*)d_out;

    k_pool<<<dim3(TLEN / STRIP, BATCH * NBANDS), 256>>>(x, log_gamma, diff_w, diff_b);
    k_act <<<dim3(TLEN / ACHUNK, BATCH), 256>>>(avg_w, avg_b, mix_w, gauss_w, gauss_b);
    k_norm<<<BATCH * TLEN / 4 / 256, 256>>>(out);
}

// round 4
// speedup vs baseline: 1.4431x; 1.4431x over previous
#include <cuda_runtime.h>
#include <cstdint>

// Problem constants (fixed by setup_inputs): x is [8, 512, 16384] fp32.
#define BATCH   8
#define NBANDS  8
#define FBAND   64          // 512 / 8
#define TLEN    16384
#define NDIFF   5
#define NAVG    11
#define NGAUSS  15
#define STRIP   2048        // time-strip per k_pool block (256 thr * 8 t)

// Scratch (allocation-free rule: __device__ globals)
__device__ float    g_pool[BATCH * NBANDS * TLEN];   // 4 MB
__device__ float    g_act [BATCH * TLEN];            // 512 KB
__device__ unsigned g_bmax[BATCH];

// log2(1 + gam*v); ln2 is folded into the diff weights so no FMUL-by-ln2 here.
__device__ __forceinline__ float lg2p(float gam, float v) {
    return __log2f(fmaf(gam, v, 1.0f));
}

// ---------------------------------------------------------------------------
// Kernel 1: the 256 MB streamer (R2 design — direct loads, branch/shfl-free).
// pool[b,c,t] = sum_f relu( sum_k diff_w[c,k]*log1p(gamma_c*x[b,c*64+f,t+k-2]) + diff_b[c] )
// Thread owns 8 contiguous t; loads its own 12-float window [t0-2, t0+10)
// every row (the two halo LDG.64s are L1 hits on neighbors' lines).
// ---------------------------------------------------------------------------
struct Row { float2 l; float4 a; float4 b; float2 r; };

__device__ __forceinline__ Row load_row(const float* __restrict__ p, int offL, int offR) {
    Row v;
    v.l = *reinterpret_cast<const float2*>(p + offL);
    v.a = *reinterpret_cast<const float4*>(p);
    v.b = *reinterpret_cast<const float4*>(p + 4);
    v.r = *reinterpret_cast<const float2*>(p + offR);
    return v;
}

__global__ void __launch_bounds__(256, 4) k_pool(
    const float* __restrict__ x,
    const float* __restrict__ log_gamma,
    const float* __restrict__ diff_w,      // [NBANDS,1,1,5] flat
    const float* __restrict__ diff_b)
{
    const int slab = blockIdx.y;                 // b*NBANDS + c
    const int c    = slab & (NBANDS - 1);
    const int tid  = threadIdx.x;
    const int t0   = blockIdx.x * STRIP + tid * 8;

    // fold the per-batch max reset into this kernel (runs before k_act in stream order)
    if (blockIdx.x == 0 && (slab & 7) == 0 && tid == 0) g_bmax[slab >> 3] = 0u;

    const float gam = __expf(log_gamma[c]);
    const float LN2 = 0.69314718055994531f;      // fold ln2 into weights -> use log2f
    const float w0 = diff_w[c * NDIFF + 0] * LN2;
    const float w1 = diff_w[c * NDIFF + 1] * LN2;
    const float w2 = diff_w[c * NDIFF + 2] * LN2;
    const float w3 = diff_w[c * NDIFF + 3] * LN2;
    const float w4 = diff_w[c * NDIFF + 4] * LN2;
    const float db = diff_b[c];

    // Edge handling once, outside the loop: clamp load offsets, mask with 0/1.
    const bool  okL  = (t0 > 0);
    const bool  okR  = (t0 + 8 < TLEN);
    const int   offL = okL ? -2 : 0;     // always a valid (8B-aligned) address
    const int   offR = okR ?  8 : 6;
    const float mL   = okL ? 1.0f : 0.0f;
    const float mR   = okR ? 1.0f : 0.0f;

    const float* base = x + (size_t)slab * FBAND * TLEN + t0;

    float acc[8];
    #pragma unroll
    for (int i = 0; i < 8; ++i) acc[i] = 0.f;

    Row cur = load_row(base, offL, offR);

    #pragma unroll 2
    for (int f = 0; f < FBAND; ++f) {
        // prefetch next row (wrap-clamped: last prefetch re-reads a hot row, harmless)
        const int fn = (f + 1) & (FBAND - 1);
        Row nxt = load_row(base + (size_t)fn * TLEN, offL, offR);

        // L[j] = log2(1 + gamma * x[t0 + j - 2]) over the 12-float window
        float L[12];
        L[0]  = mL * lg2p(gam, cur.l.x);
        L[1]  = mL * lg2p(gam, cur.l.y);
        L[2]  = lg2p(gam, cur.a.x);  L[3] = lg2p(gam, cur.a.y);
        L[4]  = lg2p(gam, cur.a.z);  L[5] = lg2p(gam, cur.a.w);
        L[6]  = lg2p(gam, cur.b.x);  L[7] = lg2p(gam, cur.b.y);
        L[8]  = lg2p(gam, cur.b.z);  L[9] = lg2p(gam, cur.b.w);
        L[10] = mR * lg2p(gam, cur.r.x);
        L[11] = mR * lg2p(gam, cur.r.y);

        #pragma unroll
        for (int i = 0; i < 8; ++i) {
            float d = fmaf(w0, L[i],
                      fmaf(w1, L[i + 1],
                      fmaf(w2, L[i + 2],
                      fmaf(w3, L[i + 3], w4 * L[i + 4])))) + db;
            acc[i] += fmaxf(d, 0.f);   // A_LRELU = 0 -> relu
        }
        cur = nxt;
    }

    float* o = g_pool + (size_t)slab * TLEN + t0;
    *reinterpret_cast<float4*>(o)     = make_float4(acc[0], acc[1], acc[2], acc[3]);
    *reinterpret_cast<float4*>(o + 4) = make_float4(acc[4], acc[5], acc[6], acc[7]);
}

// ---------------------------------------------------------------------------
// Kernel 2: mix + avg + gauss + relu + per-batch max. Wide grid (16 x 8 blocks).
//   u[t] = sum_c mix_w[c] * pool[b,c,t]
//   m[t] = u[t] - (avg_w (x) u)[t] - sum_c mix_w[c]*avg_b[c]   (band-uniform avg_w)
//   act  = relu((gauss_w (x) m)[t] + gauss_b)
// ---------------------------------------------------------------------------
#define ACHUNK 1024
#define UH 12      // 5 (avg) + 7 (gauss)
#define MH 7

__global__ void __launch_bounds__(256) k_act(
    const float* __restrict__ avg_w,    // [8,1,11] flat; band-0 taps (uniform)
    const float* __restrict__ avg_b,
    const float* __restrict__ mix_w,
    const float* __restrict__ gauss_w,  // [1,1,15] flat
    const float* __restrict__ gauss_b)
{
    __shared__ float su[ACHUNK + 2 * UH];
    __shared__ float sm[ACHUNK + 2 * MH];
    __shared__ float sred[8];

    const int b   = blockIdx.y;
    const int t0  = blockIdx.x * ACHUNK;
    const int tid = threadIdx.x;

    float mw[NBANDS];
    #pragma unroll
    for (int c = 0; c < NBANDS; ++c) mw[c] = mix_w[c];
    float aw[NAVG];
    #pragma unroll
    for (int k = 0; k < NAVG; ++k) aw[k] = avg_w[k];
    float CB = 0.f;
    #pragma unroll
    for (int c = 0; c < NBANDS; ++c) CB = fmaf(mw[c], avg_b[c], CB);
    float gw[NGAUSS];
    #pragma unroll
    for (int k = 0; k < NGAUSS; ++k) gw[k] = gauss_w[k];
    const float gb = gauss_b[0];

    const float* pb = g_pool + (size_t)b * NBANDS * TLEN;

    // stage u chunk + halo (zero-padded outside [0, TLEN)); u computed on the fly
    for (int i = tid; i < ACHUNK + 2 * UH; i += 256) {
        const int gt = t0 - UH + i;
        float v = 0.f;
        if (gt >= 0 && gt < TLEN) {
            #pragma unroll
            for (int c = 0; c < NBANDS; ++c)
                v = fmaf(mw[c], pb[c * TLEN + gt], v);
        }
        su[i] = v;
    }
    __syncthreads();

    // m chunk + halo (m zero-padded outside [0, TLEN) for the gauss conv)
    for (int i = tid; i < ACHUNK + 2 * MH; i += 256) {
        const int gt = t0 - MH + i;
        float mval = 0.f;
        if (gt >= 0 && gt < TLEN) {
            const int bidx = i + (UH - MH);   // su index of global gt
            float a = 0.f;
            #pragma unroll
            for (int k = 0; k < NAVG; ++k)
                a = fmaf(aw[k], su[bidx + k - 5], a);
            mval = su[bidx] - a - CB;
        }
        sm[i] = mval;
    }
    __syncthreads();

    float mx = 0.f;
    float* ao = g_act + (size_t)b * TLEN + t0;
    #pragma unroll
    for (int j = 0; j < ACHUNK / 256; ++j) {
        const int tl = tid + j * 256;
        float g = gb;
        #pragma unroll
        for (int k = 0; k < NGAUSS; ++k)
            g = fmaf(gw[k], sm[tl + k], g);
        const float a = fmaxf(g, 0.f);
        ao[tl] = a;
        mx = fmaxf(mx, a);
    }

    // block max reduce -> atomicMax (values >= 0, so uint order == float order)
    #pragma unroll
    for (int o = 16; o > 0; o >>= 1)
        mx = fmaxf(mx, __shfl_xor_sync(0xffffffffu, mx, o));
    if ((tid & 31) == 0) sred[tid >> 5] = mx;
    __syncthreads();
    if (tid < 8) {
        mx = sred[tid];
        #pragma unroll
        for (int o = 4; o > 0; o >>= 1)
            mx = fmaxf(mx, __shfl_xor_sync(0xffu, mx, o));
        if (tid == 0) atomicMax(&g_bmax[b], __float_as_uint(mx));
    }
}

// ---------------------------------------------------------------------------
// Kernel 3: out = act / (max_b + 1e-8)
// ---------------------------------------------------------------------------
__global__ void __launch_bounds__(256) k_norm(float* __restrict__ out)
{
    const int v = blockIdx.x * 256 + threadIdx.x;   // float4 index over BATCH*TLEN/4
    const int b = v / (TLEN / 4);
    const float mxv = __uint_as_float(g_bmax[b]);
    const float inv = 1.0f / (mxv + 1e-8f);
    float4 q = reinterpret_cast<const float4*>(g_act)[v];
    q.x *= inv; q.y *= inv; q.z *= inv; q.w *= inv;
    reinterpret_cast<float4*>(out)[v] = q;
}

// ---------------------------------------------------------------------------
// Inputs (metadata order): x, log_gamma, diff_w, diff_b, avg_w, avg_b,
//                          mix_w, gauss_w, gauss_b. Output: [8, 16384] fp32.
// ---------------------------------------------------------------------------
extern "C" void kernel_launch(void* const* d_in, const int* in_sizes, int n_in,
                              void* d_out, int out_size)
{
    const float* x         = (const float*)d_in[0];
    const float* log_gamma = (const float*)d_in[1];
    const float* diff_w    = (const float*)d_in[2];
    const float* diff_b    = (const float*)d_in[3];
    const float* avg_w     = (const float*)d_in[4];
    const float* avg_b     = (const float*)d_in[5];
    const float* mix_w     = (const float*)d_in[6];
    const float* gauss_w   = (const float*)d_in[7];
    const float* gauss_b   = (const float*)d_in[8];
    float* out = (float*)d_out;

    k_pool<<<dim3(TLEN / STRIP, BATCH * NBANDS), 256>>>(x, log_gamma, diff_w, diff_b);
    k_act <<<dim3(TLEN / ACHUNK, BATCH), 256>>>(avg_w, avg_b, mix_w, gauss_w, gauss_b);
    k_norm<<<BATCH * TLEN / 4 / 256, 256>>>(out);
}

// round 5
// speedup vs baseline: 1.5535x; 1.0765x over previous
#include <cuda_runtime.h>
#include <cstdint>

// Problem constants (fixed by setup_inputs): x is [8, 512, 16384] fp32.
#define BATCH   8
#define NBANDS  8
#define FBAND   64          // 512 / 8
#define TLEN    16384
#define NDIFF   5
#define NAVG    11
#define NGAUSS  15
#define STRIP   1024        // time-strip per k_pool block (128 thr * 8 t)

#define ACHUNK  1024
#define NBLK_TAIL ((TLEN / ACHUNK) * BATCH)   // 128 tail blocks, all co-resident

// Scratch (allocation-free rule: __device__ globals)
__device__ float    g_pool[BATCH * NBANDS * TLEN];   // 4 MB
__device__ unsigned g_bmax[BATCH];
__device__ unsigned g_sync;                          // tail grid-barrier counter
__device__ __align__(8) float g_zero2[2] = {0.f, 0.f};  // zero-pad page for halos

// log2(1 + gam*v); ln2 is folded into the diff weights so no FMUL-by-ln2 here.
__device__ __forceinline__ float lg2p(float gam, float v) {
    return __log2f(fmaf(gam, v, 1.0f));
}

// ---------------------------------------------------------------------------
// Kernel 1: the 256 MB streamer.
// pool[b,c,t] = sum_f relu( sum_k diff_w[c,k]*log1p(gamma_c*x[b,c*64+f,t+k-2]) + diff_b[c] )
// Thread owns 8 contiguous t; loads its own 12-float window per row (halo
// LDG.64s are L1 hits on neighbors' lines). Edge threads' halos point at a
// zero page, so log2(1+g*0)=0 provides zero-padding with NO masks/branches.
// ---------------------------------------------------------------------------
__global__ void __launch_bounds__(128, 8) k_pool(
    const float* __restrict__ x,
    const float* __restrict__ log_gamma,
    const float* __restrict__ diff_w,      // [NBANDS,1,1,5] flat
    const float* __restrict__ diff_b)
{
    const int slab = blockIdx.y;                 // b*NBANDS + c
    const int c    = slab & (NBANDS - 1);
    const int tid  = threadIdx.x;
    const int t0   = blockIdx.x * STRIP + tid * 8;

    // reset tail-kernel state (runs before k_tail in stream order)
    if (blockIdx.x == 0 && blockIdx.y == 0 && tid < BATCH + 1) {
        if (tid < BATCH) g_bmax[tid] = 0u; else g_sync = 0u;
    }

    const float gam = __expf(log_gamma[c]);
    const float LN2 = 0.69314718055994531f;      // fold ln2 into weights -> use log2f
    const float w0 = diff_w[c * NDIFF + 0] * LN2;
    const float w1 = diff_w[c * NDIFF + 1] * LN2;
    const float w2 = diff_w[c * NDIFF + 2] * LN2;
    const float w3 = diff_w[c * NDIFF + 3] * LN2;
    const float w4 = diff_w[c * NDIFF + 4] * LN2;
    const float db = diff_b[c];

    const float* base = x + (size_t)slab * FBAND * TLEN + t0;

    // halo pointers: valid neighbors, or the static zero page (stride 0)
    const bool okL = (t0 > 0);
    const bool okR = (t0 + 8 < TLEN);
    const float* pL = okL ? (base - 2) : g_zero2;
    const float* pR = okR ? (base + 8) : g_zero2;
    const int    sL = okL ? TLEN : 0;
    const int    sR = okR ? TLEN : 0;

    float acc[8];
    #pragma unroll
    for (int i = 0; i < 8; ++i) acc[i] = 0.f;

    float4 a0 = *reinterpret_cast<const float4*>(base);
    float4 b0 = *reinterpret_cast<const float4*>(base + 4);
    float2 l0 = *reinterpret_cast<const float2*>(pL);
    float2 r0 = *reinterpret_cast<const float2*>(pR);

    #pragma unroll 2
    for (int f = 0; f < FBAND; ++f) {
        // prefetch next row (wrap-clamped: last prefetch re-reads a hot row, harmless)
        const int fn = (f + 1) & (FBAND - 1);
        const float4 a1 = *reinterpret_cast<const float4*>(base + (size_t)fn * TLEN);
        const float4 b1 = *reinterpret_cast<const float4*>(base + (size_t)fn * TLEN + 4);
        const float2 l1 = *reinterpret_cast<const float2*>(pL + (size_t)fn * sL);
        const float2 r1 = *reinterpret_cast<const float2*>(pR + (size_t)fn * sR);

        // L[j] = log2(1 + gamma * x[t0 + j - 2]); zero page yields exactly 0
        float L[12];
        L[0]  = lg2p(gam, l0.x);
        L[1]  = lg2p(gam, l0.y);
        L[2]  = lg2p(gam, a0.x);  L[3] = lg2p(gam, a0.y);
        L[4]  = lg2p(gam, a0.z);  L[5] = lg2p(gam, a0.w);
        L[6]  = lg2p(gam, b0.x);  L[7] = lg2p(gam, b0.y);
        L[8]  = lg2p(gam, b0.z);  L[9] = lg2p(gam, b0.w);
        L[10] = lg2p(gam, r0.x);
        L[11] = lg2p(gam, r0.y);

        #pragma unroll
        for (int i = 0; i < 8; ++i) {
            // bias folded into the innermost fmaf (saves the trailing FADD)
            float d = fmaf(w0, L[i],
                      fmaf(w1, L[i + 1],
                      fmaf(w2, L[i + 2],
                      fmaf(w3, L[i + 3],
                      fmaf(w4, L[i + 4], db)))));
            acc[i] += fmaxf(d, 0.f);   // A_LRELU = 0 -> relu
        }
        a0 = a1; b0 = b1; l0 = l1; r0 = r1;
    }

    float* o = g_pool + (size_t)slab * TLEN + t0;
    *reinterpret_cast<float4*>(o)     = make_float4(acc[0], acc[1], acc[2], acc[3]);
    *reinterpret_cast<float4*>(o + 4) = make_float4(acc[4], acc[5], acc[6], acc[7]);
}

// ---------------------------------------------------------------------------
// Kernel 2: fused tail with software grid barrier (128 blocks, single wave).
//   u[t] = sum_c mix_w[c] * pool[b,c,t]
//   m[t] = u[t] - (avg_w (x) u)[t] - sum_c mix_w[c]*avg_b[c]   (band-uniform avg_w)
//   act  = relu((gauss_w (x) m)[t] + gauss_b)    (kept in registers)
//   atomicMax per batch -> grid barrier -> out = act / (max_b + 1e-8)
// ---------------------------------------------------------------------------
#define UH 12      // 5 (avg) + 7 (gauss)
#define MH 7

__global__ void __launch_bounds__(256) k_tail(
    const float* __restrict__ avg_w,    // [8,1,11] flat; band-0 taps (uniform)
    const float* __restrict__ avg_b,
    const float* __restrict__ mix_w,
    const float* __restrict__ gauss_w,  // [1,1,15] flat
    const float* __restrict__ gauss_b,
    float* __restrict__ out)
{
    __shared__ float su[ACHUNK + 2 * UH];
    __shared__ float sm[ACHUNK + 2 * MH];
    __shared__ float sred[8];

    const int b   = blockIdx.y;
    const int t0  = blockIdx.x * ACHUNK;
    const int tid = threadIdx.x;

    float mw[NBANDS];
    #pragma unroll
    for (int c = 0; c < NBANDS; ++c) mw[c] = mix_w[c];
    float aw[NAVG];
    #pragma unroll
    for (int k = 0; k < NAVG; ++k) aw[k] = avg_w[k];
    float CB = 0.f;
    #pragma unroll
    for (int c = 0; c < NBANDS; ++c) CB = fmaf(mw[c], avg_b[c], CB);
    float gw[NGAUSS];
    #pragma unroll
    for (int k = 0; k < NGAUSS; ++k) gw[k] = gauss_w[k];
    const float gb = gauss_b[0];

    const float* pb = g_pool + (size_t)b * NBANDS * TLEN;

    // stage u chunk + halo (zero-padded outside [0, TLEN)); u computed on the fly
    for (int i = tid; i < ACHUNK + 2 * UH; i += 256) {
        const int gt = t0 - UH + i;
        float v = 0.f;
        if (gt >= 0 && gt < TLEN) {
            #pragma unroll
            for (int c = 0; c < NBANDS; ++c)
                v = fmaf(mw[c], pb[c * TLEN + gt], v);
        }
        su[i] = v;
    }
    __syncthreads();

    // m chunk + halo (m zero-padded outside [0, TLEN) for the gauss conv)
    for (int i = tid; i < ACHUNK + 2 * MH; i += 256) {
        const int gt = t0 - MH + i;
        float mval = 0.f;
        if (gt >= 0 && gt < TLEN) {
            const int bidx = i + (UH - MH);   // su index of global gt
            float a = 0.f;
            #pragma unroll
            for (int k = 0; k < NAVG; ++k)
                a = fmaf(aw[k], su[bidx + k - 5], a);
            mval = su[bidx] - a - CB;
        }
        sm[i] = mval;
    }
    __syncthreads();

    float mx = 0.f;
    float av[ACHUNK / 256];
    #pragma unroll
    for (int j = 0; j < ACHUNK / 256; ++j) {
        const int tl = tid + j * 256;
        float g = gb;
        #pragma unroll
        for (int k = 0; k < NGAUSS; ++k)
            g = fmaf(gw[k], sm[tl + k], g);
        const float a = fmaxf(g, 0.f);
        av[j] = a;
        mx = fmaxf(mx, a);
    }

    // block max -> atomicMax (values >= 0, so uint order == float order)
    #pragma unroll
    for (int o = 16; o > 0; o >>= 1)
        mx = fmaxf(mx, __shfl_xor_sync(0xffffffffu, mx, o));
    if ((tid & 31) == 0) sred[tid >> 5] = mx;
    __syncthreads();
    if (tid == 0) {
        mx = fmaxf(fmaxf(fmaxf(sred[0], sred[1]), fmaxf(sred[2], sred[3])),
                   fmaxf(fmaxf(sred[4], sred[5]), fmaxf(sred[6], sred[7])));
        atomicMax(&g_bmax[b], __float_as_uint(mx));
        __threadfence();                       // publish my max before arriving
        atomicAdd(&g_sync, 1u);                // arrive
        volatile unsigned* vs = &g_sync;       // spin: all 128 blocks co-resident
        while (*vs < (unsigned)NBLK_TAIL) { }
    }
    __syncthreads();

    const float mxv = __uint_as_float(*(volatile unsigned*)&g_bmax[b]);
    const float inv = 1.0f / (mxv + 1e-8f);

    float* ob = out + (size_t)b * TLEN + t0;
    #pragma unroll
    for (int j = 0; j < ACHUNK / 256; ++j)
        ob[tid + j * 256] = av[j] * inv;
}

// ---------------------------------------------------------------------------
// Inputs (metadata order): x, log_gamma, diff_w, diff_b, avg_w, avg_b,
//                          mix_w, gauss_w, gauss_b. Output: [8, 16384] fp32.
// ---------------------------------------------------------------------------
extern "C" void kernel_launch(void* const* d_in, const int* in_sizes, int n_in,
                              void* d_out, int out_size)
{
    const float* x         = (const float*)d_in[0];
    const float* log_gamma = (const float*)d_in[1];
    const float* diff_w    = (const float*)d_in[2];
    const float* diff_b    = (const float*)d_in[3];
    const float* avg_w     = (const float*)d_in[4];
    const float* avg_b     = (const float*)d_in[5];
    const float* mix_w     = (const float*)d_in[6];
    const float* gauss_w   = (const float*)d_in[7];
    const float* gauss_b   = (const float*)d_in[8];
    float* out = (float*)d_out;

    k_pool<<<dim3(TLEN / STRIP, BATCH * NBANDS), 128>>>(x, log_gamma, diff_w, diff_b);
    k_tail<<<dim3(TLEN / ACHUNK, BATCH), 256>>>(avg_w, avg_b, mix_w, gauss_w, gauss_b, out);
}